// round 16
// baseline (speedup 1.0000x reference)
#include <cuda_runtime.h>
#include <cuda_fp16.h>
#include <math.h>
#include <stdint.h>

// ---------------- problem constants ----------------
#define BATCH   32
#define CHN     384
#define HH      28
#define WW      28
#define NTOK    784
#define HEADS   12
#define HDIM    32
#define HIDDEN  1536
#define MROWS   (BATCH*NTOK)       // 25088
#define SCALE_K 0.17677669529663687f

// ---------------- scratch ----------------
__device__ float g_nchwA[BATCH*CHN*NTOK];
__device__ float g_xt[MROWS*CHN];
__device__ float g_x2[MROWS*CHN];
__device__ float g_x3[MROWS*CHN];
__device__ float g_attn[BATCH*HEADS*HDIM*HDIM];
// fp16 activations
__device__ __align__(16) __half g_qkvH[(size_t)MROWS*3*CHN];
__device__ __align__(16) __half g_curH[(size_t)MROWS*CHN];
__device__ __align__(16) __half g_aoH[(size_t)MROWS*CHN];
__device__ __align__(16) __half g_hidH[(size_t)MROWS*HIDDEN];
// fp16 weights [N, K]
__device__ __align__(16) __half g_wqkvH[(size_t)(3*CHN)*CHN];
__device__ __align__(16) __half g_wprojH[(size_t)CHN*CHN];
__device__ __align__(16) __half g_wfc1H[(size_t)HIDDEN*CHN];
__device__ __align__(16) __half g_wfc2H[(size_t)CHN*HIDDEN];

// ---------------- helpers ----------------
__device__ __forceinline__ uint32_t smem_u32(const void* p) {
    uint32_t a;
    asm("{ .reg .u64 t; cvta.to.shared.u64 t, %1; cvt.u32.u64 %0, t; }" : "=r"(a) : "l"(p));
    return a;
}
#define CP16(dst, src) \
    asm volatile("cp.async.cg.shared.global [%0], [%1], 16;" :: "r"(dst), "l"(src))
#define CP_COMMIT() asm volatile("cp.async.commit_group;" ::: "memory")
#define CP_WAIT1()  asm volatile("cp.async.wait_group 1;" ::: "memory")

#define LDMX4(r0,r1,r2,r3,addr) \
    asm volatile("ldmatrix.sync.aligned.m8n8.x4.shared.b16 {%0,%1,%2,%3}, [%4];" \
                 : "=r"(r0), "=r"(r1), "=r"(r2), "=r"(r3) : "r"(addr))

#define MMA16816(d, a, b) \
    asm volatile("mma.sync.aligned.m16n8k16.row.col.f32.f16.f16.f32 " \
        "{%0,%1,%2,%3}, {%4,%5,%6,%7}, {%8,%9}, {%0,%1,%2,%3};" \
        : "+f"((d)[0]), "+f"((d)[1]), "+f"((d)[2]), "+f"((d)[3]) \
        : "r"((a)[0]), "r"((a)[1]), "r"((a)[2]), "r"((a)[3]), "r"((b)[0]), "r"((b)[1]))

__device__ __forceinline__ float warp_sum(float s) {
    #pragma unroll
    for (int o = 16; o > 0; o >>= 1) s += __shfl_xor_sync(0xffffffffu, s, o);
    return s;
}
__device__ __forceinline__ float warp_max(float s) {
    #pragma unroll
    for (int o = 16; o > 0; o >>= 1) s = fmaxf(s, __shfl_xor_sync(0xffffffffu, s, o));
    return s;
}

// ---------------- plain fp16 mma.sync GEMM, BK=64, 3-stage ring (R12 proven) ----------------
#define STG_SZ    32768
#define GEMM_SMEM (3*STG_SZ)

__device__ __forceinline__ void issue_chunk(
    uint32_t sb, int st, const char* Ab, const char* Bb,
    int m0, int n0, int Kb, int kk, int tid)
{
    uint32_t sA = sb + st * STG_SZ;
    uint32_t sB = sA + 16384;
    #pragma unroll
    for (int i = 0; i < 4; i++) {
        int id = tid + (i << 8);
        int r = id >> 3, c = id & 7;
        const char* g = Ab + (((size_t)(m0 + r) * Kb + kk + (c << 3)) << 1);
        uint32_t d = sA + (r << 7) + ((c ^ (r & 7)) << 4);
        CP16(d, g);
    }
    #pragma unroll
    for (int i = 0; i < 4; i++) {
        int id = tid + (i << 8);
        int r = id >> 3, c = id & 7;
        const char* g = Bb + (((size_t)(n0 + r) * Kb + kk + (c << 3)) << 1);
        uint32_t d = sB + (r << 7) + ((c ^ (r & 7)) << 4);
        CP16(d, g);
    }
}

__global__ void __launch_bounds__(256, 2) gemm_mma(
    const __half* __restrict__ A, const __half* __restrict__ Bw,
    const float* __restrict__ bias, const float* __restrict__ res,
    float* __restrict__ outF, __half* __restrict__ outS,
    int Ntot, int Kb, int mode)
{
    extern __shared__ __align__(128) char smem[];
    uint32_t sb = smem_u32(smem);
    int tid = threadIdx.x, lane = tid & 31, w = tid >> 5;
    int wm0 = (w & 1) * 64;
    int wn0 = (w >> 1) * 32;
    int m0 = blockIdx.y * 128, n0 = blockIdx.x * 128;

    const char* Ab = (const char*)A;
    const char* Bb = (const char*)Bw;
    int nch = Kb >> 6;

    float acc[4][4][4];
    #pragma unroll
    for (int i = 0; i < 4; i++)
        #pragma unroll
        for (int j2 = 0; j2 < 4; j2++)
            #pragma unroll
            for (int q = 0; q < 4; q++) acc[i][j2][q] = 0.f;

    issue_chunk(sb, 0, Ab, Bb, m0, n0, Kb, 0,  tid); CP_COMMIT();
    issue_chunk(sb, 1, Ab, Bb, m0, n0, Kb, 64, tid); CP_COMMIT();

    for (int ch = 0; ch < nch; ch++) {
        CP_WAIT1();
        __syncthreads();
        if (ch + 2 < nch)
            issue_chunk(sb, (ch + 2) % 3, Ab, Bb, m0, n0, Kb, (ch + 2) << 6, tid);
        CP_COMMIT();

        uint32_t sA = sb + (ch % 3) * STG_SZ;
        uint32_t sB = sA + 16384;

        #pragma unroll
        for (int ks = 0; ks < 4; ks++) {
            uint32_t a[4][4], b[4][2];
            uint32_t kcA = (ks << 1) + (lane >> 4);
            #pragma unroll
            for (int mt = 0; mt < 4; mt++) {
                uint32_t r = wm0 + mt * 16 + (lane & 15);
                uint32_t addr = sA + (r << 7) + ((kcA ^ (r & 7)) << 4);
                LDMX4(a[mt][0], a[mt][1], a[mt][2], a[mt][3], addr);
            }
            #pragma unroll
            for (int ntp = 0; ntp < 2; ntp++) {
                uint32_t j = lane >> 3;
                uint32_t nt = ntp * 2 + (j >> 1);
                uint32_t kc = (ks << 1) + (j & 1);
                uint32_t r = wn0 + nt * 8 + (lane & 7);
                uint32_t addr = sB + (r << 7) + ((kc ^ (r & 7)) << 4);
                uint32_t q0, q1, q2, q3;
                LDMX4(q0, q1, q2, q3, addr);
                b[ntp*2][0] = q0;   b[ntp*2][1] = q1;
                b[ntp*2+1][0] = q2; b[ntp*2+1][1] = q3;
            }
            #pragma unroll
            for (int mt = 0; mt < 4; mt++)
                #pragma unroll
                for (int nt = 0; nt < 4; nt++)
                    MMA16816(acc[mt][nt], a[mt], b[nt]);
        }
    }

    int mrow = wm0 + (lane >> 2);
    int ncol = wn0 + (lane & 3) * 2;

    if (mode == 3) {
        __syncthreads();
        float* sf = (float*)smem;
        #pragma unroll
        for (int mt = 0; mt < 4; mt++) {
            #pragma unroll
            for (int nt = 0; nt < 4; nt++) {
                int ml = mrow + mt * 16;
                int nl = ncol + nt * 8;
                int m = m0 + ml, n = n0 + nl;
                float v0 = acc[mt][nt][0], v1 = acc[mt][nt][1];
                float v2 = acc[mt][nt][2], v3 = acc[mt][nt][3];
                float2 bb = *(const float2*)(bias + n);
                float2 r0 = *(const float2*)(res + (size_t)m * Ntot + n);
                float2 r1 = *(const float2*)(res + (size_t)(m+8) * Ntot + n);
                v0 += bb.x + r0.x; v1 += bb.y + r0.y;
                v2 += bb.x + r1.x; v3 += bb.y + r1.y;
                sf[nl * 129 + ml]           = v0;
                sf[(nl + 1) * 129 + ml]     = v1;
                sf[nl * 129 + ml + 8]       = v2;
                sf[(nl + 1) * 129 + ml + 8] = v3;
            }
        }
        __syncthreads();
        #pragma unroll 1
        for (int ci = 0; ci < 16; ci++) {
            int cl = w + ci * 8;
            int cg = n0 + cl;
            #pragma unroll
            for (int rep = 0; rep < 4; rep++) {
                int tl = rep * 32 + lane;
                int m = m0 + tl;
                int b = m / NTOK;
                int t = m - b * NTOK;
                outF[(size_t)b * (CHN*NTOK) + (size_t)cg * NTOK + t] = sf[cl * 129 + tl];
            }
        }
        return;
    }

    #pragma unroll
    for (int mt = 0; mt < 4; mt++) {
        #pragma unroll
        for (int nt = 0; nt < 4; nt++) {
            int m = m0 + mrow + mt * 16;
            int n = n0 + ncol + nt * 8;
            float v0 = acc[mt][nt][0], v1 = acc[mt][nt][1];
            float v2 = acc[mt][nt][2], v3 = acc[mt][nt][3];
            if (bias) {
                float2 bb = *(const float2*)(bias + n);
                v0 += bb.x; v1 += bb.y; v2 += bb.x; v3 += bb.y;
            }
            if (mode == 1) {
                v0 = 0.5f*v0*(1.0f+erff(v0*0.70710678118654752f));
                v1 = 0.5f*v1*(1.0f+erff(v1*0.70710678118654752f));
                v2 = 0.5f*v2*(1.0f+erff(v2*0.70710678118654752f));
                v3 = 0.5f*v3*(1.0f+erff(v3*0.70710678118654752f));
            }
            if (mode != 0) {
                __half2 p0; p0.x = __float2half(v0); p0.y = __float2half(v1);
                __half2 p1; p1.x = __float2half(v2); p1.y = __float2half(v3);
                *(__half2*)(outS + (size_t)m * Ntot + n) = p0;
                *(__half2*)(outS + (size_t)(m+8) * Ntot + n) = p1;
            } else {
                if (res) {
                    float2 r0 = *(const float2*)(res + (size_t)m * Ntot + n);
                    float2 r1 = *(const float2*)(res + (size_t)(m+8) * Ntot + n);
                    v0 += r0.x; v1 += r0.y; v2 += r1.x; v3 += r1.y;
                }
                float2 o0; o0.x = v0; o0.y = v1;
                float2 o1; o1.x = v2; o1.y = v3;
                *(float2*)(outF + (size_t)m * Ntot + n) = o0;
                *(float2*)(outF + (size_t)(m+8) * Ntot + n) = o1;
            }
        }
    }
}

// ---------------- weight convert (all four in one launch): fp32 -> fp16 ----------------
__global__ void weight_conv_all(
    const float* __restrict__ w0, __half* __restrict__ o0,
    const float* __restrict__ w1, __half* __restrict__ o1,
    const float* __restrict__ w2, __half* __restrict__ o2,
    const float* __restrict__ w3, __half* __restrict__ o3)
{
    int seg = blockIdx.y;
    const float* w; __half* o; int cnt;
    if (seg == 0)      { w = w0; o = o0; cnt = 3*CHN*CHN;  }
    else if (seg == 1) { w = w1; o = o1; cnt = CHN*CHN;    }
    else if (seg == 2) { w = w2; o = o2; cnt = HIDDEN*CHN; }
    else               { w = w3; o = o3; cnt = CHN*HIDDEN; }
    int idx = blockIdx.x * 256 + threadIdx.x;
    if (idx < cnt) o[idx] = __float2half(w[idx]);
}

// ---------------- depthwise 3x3 conv + residual (NCHW) ----------------
__global__ void dwconv_res(const float* __restrict__ x, const float* __restrict__ w,
                           const float* __restrict__ bias, float* __restrict__ y)
{
    int bc = blockIdx.x;
    int c  = bc % CHN;
    const float* xp = x + (size_t)bc * NTOK;
    float*       yp = y + (size_t)bc * NTOK;

    __shared__ float s[NTOK];
    __shared__ float wk[9];
    for (int i = threadIdx.x; i < NTOK; i += blockDim.x) s[i] = xp[i];
    if (threadIdx.x < 9) wk[threadIdx.x] = w[c*9 + threadIdx.x];
    __syncthreads();

    float bb = bias[c];
    for (int i = threadIdx.x; i < NTOK; i += blockDim.x) {
        int h = i / WW, q = i % WW;
        float acc = bb;
        #pragma unroll
        for (int dh = -1; dh <= 1; dh++)
            #pragma unroll
            for (int dw = -1; dw <= 1; dw++) {
                int hh = h + dh, ww2 = q + dw;
                if (hh >= 0 && hh < HH && ww2 >= 0 && ww2 < WW)
                    acc += wk[(dh+1)*3 + (dw+1)] * s[hh*WW + ww2];
            }
        yp[i] = s[i] + acc;
    }
}

// ---------------- fused transpose (NCHW -> token-major) + LayerNorm -> fp16 ----------------
#define TLN_SMEM (32*385*4)
__global__ void trans_ln(const float* __restrict__ in, const float* __restrict__ g,
                         const float* __restrict__ bt,
                         float* __restrict__ xt, __half* __restrict__ cur)
{
    extern __shared__ float st[];          // [32][385]
    int b = blockIdx.y;
    int tok0 = blockIdx.x * 32;
    int tid = threadIdx.x, tx = tid & 31, tyg = tid >> 5;

    #pragma unroll 1
    for (int cg = 0; cg < 12; cg++) {
        #pragma unroll
        for (int i = 0; i < 4; i++) {
            int c = cg * 32 + tyg + i * 8;
            int tok = tok0 + tx;
            float v = (tok < NTOK) ? in[(size_t)b * (CHN*NTOK) + (size_t)c * NTOK + tok] : 0.f;
            st[tx * 385 + c] = v;
        }
    }
    __syncthreads();

    int lane = tid & 31;
    #pragma unroll 1
    for (int p = 0; p < 4; p++) {
        int tk = tyg + p * 8;
        int tok = tok0 + tk;
        if (tok >= NTOK) continue;
        float vals[12];
        float s = 0.f;
        #pragma unroll
        for (int j = 0; j < 12; j++) { vals[j] = st[tk * 385 + lane + 32*j]; s += vals[j]; }
        s = warp_sum(s);
        float mean = s * (1.0f/CHN);
        float s2 = 0.f;
        #pragma unroll
        for (int j = 0; j < 12; j++) { float d = vals[j] - mean; s2 += d * d; }
        s2 = warp_sum(s2);
        float rstd = rsqrtf(s2 * (1.0f/CHN) + 1e-5f);

        size_t row = ((size_t)b * NTOK + tok) * CHN;
        #pragma unroll
        for (int j = 0; j < 12; j++) {
            int cidx = lane + 32*j;
            float v = vals[j];
            xt[row + cidx] = v;
            cur[row + cidx] = __float2half((v - mean) * rstd * g[cidx] + bt[cidx]);
        }
    }
}

// ---------------- token-major depthwise 3x3 + residual ----------------
__global__ void dwconv_tok(const float* __restrict__ t, const float* __restrict__ w,
                           const float* __restrict__ bias, float* __restrict__ y)
{
    __shared__ float sw[CHN*9];
    int b = blockIdx.y, h = blockIdx.x;
    int c = threadIdx.x;                 // 384 threads
    for (int i = c; i < CHN*9; i += CHN) sw[i] = w[i];
    __syncthreads();

    float wr[9];
    #pragma unroll
    for (int j = 0; j < 9; j++) wr[j] = sw[c*9 + j];
    float bb = bias[c];

    const float* tb = t + (size_t)b * NTOK * CHN;
    float* yb = y + (size_t)b * NTOK * CHN;

    for (int q = 0; q < WW; q++) {
        float acc = bb;
        float center = 0.f;
        #pragma unroll
        for (int dh = -1; dh <= 1; dh++) {
            int hh = h + dh;
            if ((unsigned)hh >= HH) continue;
            #pragma unroll
            for (int dw = -1; dw <= 1; dw++) {
                int ww2 = q + dw;
                if ((unsigned)ww2 >= WW) continue;
                float val = __ldg(tb + (size_t)(hh*WW + ww2) * CHN + c);
                acc += wr[(dh+1)*3 + (dw+1)] * val;
                if (dh == 0 && dw == 0) center = val;
            }
        }
        yb[(size_t)(h*WW + q) * CHN + c] = center + acc;
    }
}

// ---------------- layernorm (token-major in) -> fp16 ----------------
__global__ void layernorm_h(const float* __restrict__ in, const float* __restrict__ g,
                            const float* __restrict__ bt, __half* __restrict__ out)
{
    int row = blockIdx.x;
    int tid = threadIdx.x;          // 128
    int lane = tid & 31, wid = tid >> 5;
    const float* ip = in + (size_t)row * CHN;

    float v0 = ip[tid], v1 = ip[tid+128], v2 = ip[tid+256];
    __shared__ float sred[8];

    float s = warp_sum(v0 + v1 + v2);
    if (lane == 0) sred[wid] = s;
    __syncthreads();
    float mean = (sred[0]+sred[1]+sred[2]+sred[3]) * (1.0f/CHN);

    float d0 = v0-mean, d1 = v1-mean, d2 = v2-mean;
    float s2 = warp_sum(d0*d0 + d1*d1 + d2*d2);
    if (lane == 0) sred[4+wid] = s2;
    __syncthreads();
    float var = (sred[4]+sred[5]+sred[6]+sred[7]) * (1.0f/CHN);
    float rstd = rsqrtf(var + 1e-5f);

    __half* op = out + (size_t)row * CHN;
    op[tid]     = __float2half(d0*rstd*g[tid]     + bt[tid]);
    op[tid+128] = __float2half(d1*rstd*g[tid+128] + bt[tid+128]);
    op[tid+256] = __float2half(d2*rstd*g[tid+256] + bt[tid+256]);
}

// ---------------- channel attention: K^T V + fused softmax ----------------
__global__ void attn_kv_sm(const __half* __restrict__ qkv, float* __restrict__ attn)
{
    int bh = blockIdx.x;
    int b = bh / HEADS, h = bh % HEADS;
    const __half* kb = qkv + (size_t)b * NTOK * (3*CHN) + CHN   + h*HDIM;
    const __half* vb = qkv + (size_t)b * NTOK * (3*CHN) + 2*CHN + h*HDIM;

    __shared__ float ks[32][33], vs[32][33];
    int e  = threadIdx.x & 31;
    int dg = threadIdx.x >> 5;
    float acc[4] = {0.f, 0.f, 0.f, 0.f};

    for (int n0 = 0; n0 < NTOK; n0 += 32) {
        #pragma unroll
        for (int r = 0; r < 4; r++) {
            int nl = (threadIdx.x >> 5) + r*8;
            int n = n0 + nl;
            ks[nl][e] = (n < NTOK) ? __half2float(kb[(size_t)n * (3*CHN) + e]) : 0.f;
            vs[nl][e] = (n < NTOK) ? __half2float(vb[(size_t)n * (3*CHN) + e]) : 0.f;
        }
        __syncthreads();
        #pragma unroll 8
        for (int nl = 0; nl < 32; nl++) {
            float vv = vs[nl][e];
            #pragma unroll
            for (int i = 0; i < 4; i++) acc[i] = fmaf(ks[nl][dg + 8*i], vv, acc[i]);
        }
        __syncthreads();
    }
    #pragma unroll
    for (int i = 0; i < 4; i++) {
        float v = acc[i] * SCALE_K;
        float mx = warp_max(v);
        float ex = expf(v - mx);
        float s = warp_sum(ex);
        int d = dg + 8*i;
        attn[(size_t)bh * (HDIM*HDIM) + d*HDIM + e] = ex / s;
    }
}

// ---------------- tensor-core attention apply: ao = q @ attn^T ----------------
// Per block: (b,h), 64-token tile, 128 threads (4 warps, each one 16-row m-tile).
// A = q rows [m][e] fp16; B = attn rows [d][e] fp32->fp16. Both smem, 64B rows,
// swizzle c' = c ^ (r&3).  M=64, N=32, K=32 (2 k-steps).
__global__ void __launch_bounds__(128) attn_apply_mma(
    const __half* __restrict__ qkv, const float* __restrict__ attn,
    __half* __restrict__ out)
{
    __shared__ __align__(128) __half qs[64*32];    // 4KB, swizzled
    __shared__ __align__(128) __half as[32*32];    // 2KB, swizzled
    uint32_t sq = smem_u32(qs);
    uint32_t sa = smem_u32(as);

    int bh = blockIdx.x;
    int b = bh / HEADS, h = bh % HEADS;
    int m0 = blockIdx.y * 64;
    int tid = threadIdx.x, lane = tid & 31, w = tid >> 5;

    // load q tile: 64 rows x 4 chunks (16B each); 256 chunks over 128 threads
    const __half* qb = qkv + (size_t)b * NTOK * (3*CHN) + h*HDIM;
    #pragma unroll
    for (int i = 0; i < 2; i++) {
        int id = tid + (i << 7);
        int r = id >> 2, c = id & 3;
        uint32_t d = sq + (r << 6) + ((c ^ (r & 3)) << 4);
        int m = m0 + r;
        uint4 v = make_uint4(0u, 0u, 0u, 0u);
        if (m < NTOK) v = *(const uint4*)(qb + (size_t)m * (3*CHN) + (c << 3));
        *(uint4*)((char*)qs + (d - sq)) = v;
    }
    // load attn 32x32 fp32 -> fp16: thread t handles row t>>2, chunk t&3 (8 vals)
    {
        int r = tid >> 2, c = tid & 3;
        const float* ap = attn + (size_t)bh * (HDIM*HDIM) + r * HDIM + (c << 3);
        __half hv[8];
        #pragma unroll
        for (int j = 0; j < 8; j++) hv[j] = __float2half(ap[j]);
        uint32_t d = sa + (r << 6) + ((c ^ (r & 3)) << 4);
        *(uint4*)((char*)as + (d - sa)) = *(uint4*)hv;
    }
    __syncthreads();

    float acc[4][4];
    #pragma unroll
    for (int i = 0; i < 4; i++)
        #pragma unroll
        for (int q = 0; q < 4; q++) acc[i][q] = 0.f;

    #pragma unroll
    for (int ks = 0; ks < 2; ks++) {
        uint32_t a[4], bfr[4][2];
        {   // A frag: rows w*16 + (lane&15), chunk kc = 2ks + (lane>>4)
            uint32_t r = (w << 4) + (lane & 15);
            uint32_t kc = (ks << 1) + (lane >> 4);
            uint32_t addr = sq + (r << 6) + ((kc ^ (r & 3)) << 4);
            LDMX4(a[0], a[1], a[2], a[3], addr);
        }
        #pragma unroll
        for (int ntp = 0; ntp < 2; ntp++) {
            uint32_t j = lane >> 3;
            uint32_t nt = ntp * 2 + (j >> 1);
            uint32_t kc = (ks << 1) + (j & 1);
            uint32_t r = nt * 8 + (lane & 7);
            uint32_t addr = sa + (r << 6) + ((kc ^ (r & 3)) << 4);
            uint32_t q0, q1, q2, q3;
            LDMX4(q0, q1, q2, q3, addr);
            bfr[ntp*2][0] = q0;   bfr[ntp*2][1] = q1;
            bfr[ntp*2+1][0] = q2; bfr[ntp*2+1][1] = q3;
        }
        #pragma unroll
        for (int nt = 0; nt < 4; nt++)
            MMA16816(acc[nt], a, bfr[nt]);
    }

    // epilogue: m = m0 + w*16 + (lane>>2) (+8), n = nt*8 + (lane&3)*2
    __half* ob = out + (size_t)b * NTOK * CHN + h*HDIM;
    int mrow = (w << 4) + (lane >> 2);
    int ncol = (lane & 3) * 2;
    #pragma unroll
    for (int nt = 0; nt < 4; nt++) {
        int n = nt * 8 + ncol;
        int m = m0 + mrow;
        if (m < NTOK) {
            __half2 p; p.x = __float2half(acc[nt][0]); p.y = __float2half(acc[nt][1]);
            *(__half2*)(ob + (size_t)m * CHN + n) = p;
        }
        if (m + 8 < NTOK) {
            __half2 p; p.x = __float2half(acc[nt][2]); p.y = __float2half(acc[nt][3]);
            *(__half2*)(ob + (size_t)(m+8) * CHN + n) = p;
        }
    }
}

// ---------------- host launcher ----------------
extern "C" void kernel_launch(void* const* d_in, const int* in_sizes, int n_in,
                              void* d_out, int out_size)
{
    const float* x      = (const float*)d_in[0];
    const float* cpe1_w = (const float*)d_in[1];
    const float* cpe1_b = (const float*)d_in[2];
    const float* n1_g   = (const float*)d_in[3];
    const float* n1_b   = (const float*)d_in[4];
    const float* qkv_w  = (const float*)d_in[5];
    const float* proj_w = (const float*)d_in[6];
    const float* proj_b = (const float*)d_in[7];
    const float* cpe2_w = (const float*)d_in[8];
    const float* cpe2_b = (const float*)d_in[9];
    const float* n2_g   = (const float*)d_in[10];
    const float* n2_b   = (const float*)d_in[11];
    const float* fc1_w  = (const float*)d_in[12];
    const float* fc1_b  = (const float*)d_in[13];
    const float* fc2_w  = (const float*)d_in[14];
    const float* fc2_b  = (const float*)d_in[15];
    float* out = (float*)d_out;

    float *p_nchwA, *p_xt, *p_attn, *p_x2, *p_x3;
    __half *p_qkvH, *p_curH, *p_aoH, *p_hidH, *p_wqkvH, *p_wprojH, *p_wfc1H, *p_wfc2H;
    cudaGetSymbolAddress((void**)&p_nchwA,  g_nchwA);
    cudaGetSymbolAddress((void**)&p_xt,     g_xt);
    cudaGetSymbolAddress((void**)&p_attn,   g_attn);
    cudaGetSymbolAddress((void**)&p_x2,     g_x2);
    cudaGetSymbolAddress((void**)&p_x3,     g_x3);
    cudaGetSymbolAddress((void**)&p_qkvH,   g_qkvH);
    cudaGetSymbolAddress((void**)&p_curH,   g_curH);
    cudaGetSymbolAddress((void**)&p_aoH,    g_aoH);
    cudaGetSymbolAddress((void**)&p_hidH,   g_hidH);
    cudaGetSymbolAddress((void**)&p_wqkvH,  g_wqkvH);
    cudaGetSymbolAddress((void**)&p_wprojH, g_wprojH);
    cudaGetSymbolAddress((void**)&p_wfc1H,  g_wfc1H);
    cudaGetSymbolAddress((void**)&p_wfc2H,  g_wfc2H);

    cudaFuncSetAttribute(gemm_mma, cudaFuncAttributeMaxDynamicSharedMemorySize, GEMM_SMEM);
    cudaFuncSetAttribute(trans_ln, cudaFuncAttributeMaxDynamicSharedMemorySize, TLN_SMEM);

    // weight converts (single launch)
    weight_conv_all<<<dim3((HIDDEN*CHN + 255)/256, 4), 256>>>(
        qkv_w, p_wqkvH, proj_w, p_wprojH, fc1_w, p_wfc1H, fc2_w, p_wfc2H);

    // 1) x = x + dwconv1(x)            (NCHW)
    dwconv_res<<<BATCH*CHN, 256>>>(x, cpe1_w, cpe1_b, p_nchwA);
    // 2) fused transpose + LN1: xt (fp32 token-major) + curH (fp16)
    trans_ln<<<dim3(25, BATCH), 256, TLN_SMEM>>>(p_nchwA, n1_g, n1_b, p_xt, p_curH);
    // 3) qkvH = cur @ qkv_w^T          (fp16 out)
    gemm_mma<<<dim3((3*CHN)/128, MROWS/128), 256, GEMM_SMEM>>>(
        p_curH, p_wqkvH, nullptr, nullptr, nullptr, p_qkvH, 3*CHN, CHN, 2);
    // 4) channel attention: K^T V + softmax fused, then tensor-core apply
    attn_kv_sm<<<BATCH*HEADS, 256>>>(p_qkvH, p_attn);
    attn_apply_mma<<<dim3(BATCH*HEADS, 13), 128>>>(p_qkvH, p_attn, p_aoH);
    // 5) x2 = xt + ao @ proj_w^T + proj_b
    gemm_mma<<<dim3(CHN/128, MROWS/128), 256, GEMM_SMEM>>>(
        p_aoH, p_wprojH, proj_b, p_xt, p_x2, nullptr, CHN, CHN, 0);
    // 6) x3 = x2 + dwconv2(x2)          (token-major)
    dwconv_tok<<<dim3(HH, BATCH), CHN>>>(p_x2, cpe2_w, cpe2_b, p_x3);
    // 7) curH = fp16(LN2(x3))
    layernorm_h<<<MROWS, 128>>>(p_x3, n2_g, n2_b, p_curH);
    // 8) hidH = fp16(gelu(cur @ fc1^T + b1))
    gemm_mma<<<dim3(HIDDEN/128, MROWS/128), 256, GEMM_SMEM>>>(
        p_curH, p_wfc1H, fc1_b, nullptr, nullptr, p_hidH, HIDDEN, CHN, 1);
    // 9) out(NCHW) = transpose(x3 + hid @ fc2^T + b2)   -- fused epilogue
    gemm_mma<<<dim3(CHN/128, MROWS/128), 256, GEMM_SMEM>>>(
        p_hidH, p_wfc2H, fc2_b, p_x3, out, nullptr, CHN, HIDDEN, 3);
}

// round 17
// speedup vs baseline: 1.5167x; 1.5167x over previous
#include <cuda_runtime.h>
#include <cuda_fp16.h>
#include <math.h>
#include <stdint.h>

// ---------------- problem constants ----------------
#define BATCH   32
#define CHN     384
#define HH      28
#define WW      28
#define NTOK    784
#define HEADS   12
#define HDIM    32
#define HIDDEN  1536
#define MROWS   (BATCH*NTOK)       // 25088
#define SCALE_K 0.17677669529663687f

// ---------------- scratch ----------------
__device__ float g_nchwA[BATCH*CHN*NTOK];
__device__ float g_xt[MROWS*CHN];
__device__ float g_x2[MROWS*CHN];
__device__ float g_x3[MROWS*CHN];
__device__ __align__(16) __half g_attnH[BATCH*HEADS*HDIM*HDIM];
// fp16 activations
__device__ __align__(16) __half g_qkvH[(size_t)MROWS*3*CHN];
__device__ __align__(16) __half g_curH[(size_t)MROWS*CHN];
__device__ __align__(16) __half g_aoH[(size_t)MROWS*CHN];
__device__ __align__(16) __half g_hidH[(size_t)MROWS*HIDDEN];
// fp16 weights [N, K]
__device__ __align__(16) __half g_wqkvH[(size_t)(3*CHN)*CHN];
__device__ __align__(16) __half g_wprojH[(size_t)CHN*CHN];
__device__ __align__(16) __half g_wfc1H[(size_t)HIDDEN*CHN];
__device__ __align__(16) __half g_wfc2H[(size_t)CHN*HIDDEN];

// ---------------- helpers ----------------
__device__ __forceinline__ uint32_t smem_u32(const void* p) {
    uint32_t a;
    asm("{ .reg .u64 t; cvta.to.shared.u64 t, %1; cvt.u32.u64 %0, t; }" : "=r"(a) : "l"(p));
    return a;
}
#define CP16(dst, src) \
    asm volatile("cp.async.cg.shared.global [%0], [%1], 16;" :: "r"(dst), "l"(src))
#define CP_COMMIT() asm volatile("cp.async.commit_group;" ::: "memory")
#define CP_WAIT1()  asm volatile("cp.async.wait_group 1;" ::: "memory")

#define LDMX4(r0,r1,r2,r3,addr) \
    asm volatile("ldmatrix.sync.aligned.m8n8.x4.shared.b16 {%0,%1,%2,%3}, [%4];" \
                 : "=r"(r0), "=r"(r1), "=r"(r2), "=r"(r3) : "r"(addr))

#define MMA16816(d, a, b) \
    asm volatile("mma.sync.aligned.m16n8k16.row.col.f32.f16.f16.f32 " \
        "{%0,%1,%2,%3}, {%4,%5,%6,%7}, {%8,%9}, {%0,%1,%2,%3};" \
        : "+f"((d)[0]), "+f"((d)[1]), "+f"((d)[2]), "+f"((d)[3]) \
        : "r"((a)[0]), "r"((a)[1]), "r"((a)[2]), "r"((a)[3]), "r"((b)[0]), "r"((b)[1]))

__device__ __forceinline__ float warp_sum(float s) {
    #pragma unroll
    for (int o = 16; o > 0; o >>= 1) s += __shfl_xor_sync(0xffffffffu, s, o);
    return s;
}
__device__ __forceinline__ float warp_max(float s) {
    #pragma unroll
    for (int o = 16; o > 0; o >>= 1) s = fmaxf(s, __shfl_xor_sync(0xffffffffu, s, o));
    return s;
}

// ---------------- plain fp16 mma.sync GEMM, BK=64, 3-stage ring (R12 proven) ----------------
#define STG_SZ    32768
#define GEMM_SMEM (3*STG_SZ)

__device__ __forceinline__ void issue_chunk(
    uint32_t sb, int st, const char* Ab, const char* Bb,
    int m0, int n0, int Kb, int kk, int tid)
{
    uint32_t sA = sb + st * STG_SZ;
    uint32_t sB = sA + 16384;
    #pragma unroll
    for (int i = 0; i < 4; i++) {
        int id = tid + (i << 8);
        int r = id >> 3, c = id & 7;
        const char* g = Ab + (((size_t)(m0 + r) * Kb + kk + (c << 3)) << 1);
        uint32_t d = sA + (r << 7) + ((c ^ (r & 7)) << 4);
        CP16(d, g);
    }
    #pragma unroll
    for (int i = 0; i < 4; i++) {
        int id = tid + (i << 8);
        int r = id >> 3, c = id & 7;
        const char* g = Bb + (((size_t)(n0 + r) * Kb + kk + (c << 3)) << 1);
        uint32_t d = sB + (r << 7) + ((c ^ (r & 7)) << 4);
        CP16(d, g);
    }
}

__global__ void __launch_bounds__(256, 2) gemm_mma(
    const __half* __restrict__ A, const __half* __restrict__ Bw,
    const float* __restrict__ bias, const float* __restrict__ res,
    float* __restrict__ outF, __half* __restrict__ outS,
    int Ntot, int Kb, int mode)
{
    extern __shared__ __align__(128) char smem[];
    uint32_t sb = smem_u32(smem);
    int tid = threadIdx.x, lane = tid & 31, w = tid >> 5;
    int wm0 = (w & 1) * 64;
    int wn0 = (w >> 1) * 32;
    int m0 = blockIdx.y * 128, n0 = blockIdx.x * 128;

    const char* Ab = (const char*)A;
    const char* Bb = (const char*)Bw;
    int nch = Kb >> 6;

    float acc[4][4][4];
    #pragma unroll
    for (int i = 0; i < 4; i++)
        #pragma unroll
        for (int j2 = 0; j2 < 4; j2++)
            #pragma unroll
            for (int q = 0; q < 4; q++) acc[i][j2][q] = 0.f;

    issue_chunk(sb, 0, Ab, Bb, m0, n0, Kb, 0,  tid); CP_COMMIT();
    issue_chunk(sb, 1, Ab, Bb, m0, n0, Kb, 64, tid); CP_COMMIT();

    for (int ch = 0; ch < nch; ch++) {
        CP_WAIT1();
        __syncthreads();
        if (ch + 2 < nch)
            issue_chunk(sb, (ch + 2) % 3, Ab, Bb, m0, n0, Kb, (ch + 2) << 6, tid);
        CP_COMMIT();

        uint32_t sA = sb + (ch % 3) * STG_SZ;
        uint32_t sB = sA + 16384;

        #pragma unroll
        for (int ks = 0; ks < 4; ks++) {
            uint32_t a[4][4], b[4][2];
            uint32_t kcA = (ks << 1) + (lane >> 4);
            #pragma unroll
            for (int mt = 0; mt < 4; mt++) {
                uint32_t r = wm0 + mt * 16 + (lane & 15);
                uint32_t addr = sA + (r << 7) + ((kcA ^ (r & 7)) << 4);
                LDMX4(a[mt][0], a[mt][1], a[mt][2], a[mt][3], addr);
            }
            #pragma unroll
            for (int ntp = 0; ntp < 2; ntp++) {
                uint32_t j = lane >> 3;
                uint32_t nt = ntp * 2 + (j >> 1);
                uint32_t kc = (ks << 1) + (j & 1);
                uint32_t r = wn0 + nt * 8 + (lane & 7);
                uint32_t addr = sB + (r << 7) + ((kc ^ (r & 7)) << 4);
                uint32_t q0, q1, q2, q3;
                LDMX4(q0, q1, q2, q3, addr);
                b[ntp*2][0] = q0;   b[ntp*2][1] = q1;
                b[ntp*2+1][0] = q2; b[ntp*2+1][1] = q3;
            }
            #pragma unroll
            for (int mt = 0; mt < 4; mt++)
                #pragma unroll
                for (int nt = 0; nt < 4; nt++)
                    MMA16816(acc[mt][nt], a[mt], b[nt]);
        }
    }

    int mrow = wm0 + (lane >> 2);
    int ncol = wn0 + (lane & 3) * 2;

    if (mode == 3) {
        __syncthreads();
        float* sf = (float*)smem;
        #pragma unroll
        for (int mt = 0; mt < 4; mt++) {
            #pragma unroll
            for (int nt = 0; nt < 4; nt++) {
                int ml = mrow + mt * 16;
                int nl = ncol + nt * 8;
                int m = m0 + ml, n = n0 + nl;
                float v0 = acc[mt][nt][0], v1 = acc[mt][nt][1];
                float v2 = acc[mt][nt][2], v3 = acc[mt][nt][3];
                float2 bb = *(const float2*)(bias + n);
                float2 r0 = *(const float2*)(res + (size_t)m * Ntot + n);
                float2 r1 = *(const float2*)(res + (size_t)(m+8) * Ntot + n);
                v0 += bb.x + r0.x; v1 += bb.y + r0.y;
                v2 += bb.x + r1.x; v3 += bb.y + r1.y;
                sf[nl * 129 + ml]           = v0;
                sf[(nl + 1) * 129 + ml]     = v1;
                sf[nl * 129 + ml + 8]       = v2;
                sf[(nl + 1) * 129 + ml + 8] = v3;
            }
        }
        __syncthreads();
        #pragma unroll 1
        for (int ci = 0; ci < 16; ci++) {
            int cl = w + ci * 8;
            int cg = n0 + cl;
            #pragma unroll
            for (int rep = 0; rep < 4; rep++) {
                int tl = rep * 32 + lane;
                int m = m0 + tl;
                int b = m / NTOK;
                int t = m - b * NTOK;
                outF[(size_t)b * (CHN*NTOK) + (size_t)cg * NTOK + t] = sf[cl * 129 + tl];
            }
        }
        return;
    }

    #pragma unroll
    for (int mt = 0; mt < 4; mt++) {
        #pragma unroll
        for (int nt = 0; nt < 4; nt++) {
            int m = m0 + mrow + mt * 16;
            int n = n0 + ncol + nt * 8;
            float v0 = acc[mt][nt][0], v1 = acc[mt][nt][1];
            float v2 = acc[mt][nt][2], v3 = acc[mt][nt][3];
            if (bias) {
                float2 bb = *(const float2*)(bias + n);
                v0 += bb.x; v1 += bb.y; v2 += bb.x; v3 += bb.y;
            }
            if (mode == 1) {
                v0 = 0.5f*v0*(1.0f+erff(v0*0.70710678118654752f));
                v1 = 0.5f*v1*(1.0f+erff(v1*0.70710678118654752f));
                v2 = 0.5f*v2*(1.0f+erff(v2*0.70710678118654752f));
                v3 = 0.5f*v3*(1.0f+erff(v3*0.70710678118654752f));
            }
            if (mode != 0) {
                __half2 p0; p0.x = __float2half(v0); p0.y = __float2half(v1);
                __half2 p1; p1.x = __float2half(v2); p1.y = __float2half(v3);
                *(__half2*)(outS + (size_t)m * Ntot + n) = p0;
                *(__half2*)(outS + (size_t)(m+8) * Ntot + n) = p1;
            } else {
                if (res) {
                    float2 r0 = *(const float2*)(res + (size_t)m * Ntot + n);
                    float2 r1 = *(const float2*)(res + (size_t)(m+8) * Ntot + n);
                    v0 += r0.x; v1 += r0.y; v2 += r1.x; v3 += r1.y;
                }
                float2 o0; o0.x = v0; o0.y = v1;
                float2 o1; o1.x = v2; o1.y = v3;
                *(float2*)(outF + (size_t)m * Ntot + n) = o0;
                *(float2*)(outF + (size_t)(m+8) * Ntot + n) = o1;
            }
        }
    }
}

// ---------------- weight convert (all four in one launch): fp32 -> fp16 ----------------
__global__ void weight_conv_all(
    const float* __restrict__ w0, __half* __restrict__ o0,
    const float* __restrict__ w1, __half* __restrict__ o1,
    const float* __restrict__ w2, __half* __restrict__ o2,
    const float* __restrict__ w3, __half* __restrict__ o3)
{
    int seg = blockIdx.y;
    const float* w; __half* o; int cnt;
    if (seg == 0)      { w = w0; o = o0; cnt = 3*CHN*CHN;  }
    else if (seg == 1) { w = w1; o = o1; cnt = CHN*CHN;    }
    else if (seg == 2) { w = w2; o = o2; cnt = HIDDEN*CHN; }
    else               { w = w3; o = o3; cnt = CHN*HIDDEN; }
    int idx = blockIdx.x * 256 + threadIdx.x;
    if (idx < cnt) o[idx] = __float2half(w[idx]);
}

// ---------------- depthwise 3x3 conv + residual (NCHW) ----------------
__global__ void dwconv_res(const float* __restrict__ x, const float* __restrict__ w,
                           const float* __restrict__ bias, float* __restrict__ y)
{
    int bc = blockIdx.x;
    int c  = bc % CHN;
    const float* xp = x + (size_t)bc * NTOK;
    float*       yp = y + (size_t)bc * NTOK;

    __shared__ float s[NTOK];
    __shared__ float wk[9];
    for (int i = threadIdx.x; i < NTOK; i += blockDim.x) s[i] = xp[i];
    if (threadIdx.x < 9) wk[threadIdx.x] = w[c*9 + threadIdx.x];
    __syncthreads();

    float bb = bias[c];
    for (int i = threadIdx.x; i < NTOK; i += blockDim.x) {
        int h = i / WW, q = i % WW;
        float acc = bb;
        #pragma unroll
        for (int dh = -1; dh <= 1; dh++)
            #pragma unroll
            for (int dw = -1; dw <= 1; dw++) {
                int hh = h + dh, ww2 = q + dw;
                if (hh >= 0 && hh < HH && ww2 >= 0 && ww2 < WW)
                    acc += wk[(dh+1)*3 + (dw+1)] * s[hh*WW + ww2];
            }
        yp[i] = s[i] + acc;
    }
}

// ---------------- fused transpose (NCHW -> token-major) + LayerNorm -> fp16 ----------------
#define TLN_SMEM (32*385*4)
__global__ void trans_ln(const float* __restrict__ in, const float* __restrict__ g,
                         const float* __restrict__ bt,
                         float* __restrict__ xt, __half* __restrict__ cur)
{
    extern __shared__ float st[];          // [32][385]
    int b = blockIdx.y;
    int tok0 = blockIdx.x * 32;
    int tid = threadIdx.x, tx = tid & 31, tyg = tid >> 5;

    #pragma unroll 1
    for (int cg = 0; cg < 12; cg++) {
        #pragma unroll
        for (int i = 0; i < 4; i++) {
            int c = cg * 32 + tyg + i * 8;
            int tok = tok0 + tx;
            float v = (tok < NTOK) ? in[(size_t)b * (CHN*NTOK) + (size_t)c * NTOK + tok] : 0.f;
            st[tx * 385 + c] = v;
        }
    }
    __syncthreads();

    int lane = tid & 31;
    #pragma unroll 1
    for (int p = 0; p < 4; p++) {
        int tk = tyg + p * 8;
        int tok = tok0 + tk;
        if (tok >= NTOK) continue;
        float vals[12];
        float s = 0.f;
        #pragma unroll
        for (int j = 0; j < 12; j++) { vals[j] = st[tk * 385 + lane + 32*j]; s += vals[j]; }
        s = warp_sum(s);
        float mean = s * (1.0f/CHN);
        float s2 = 0.f;
        #pragma unroll
        for (int j = 0; j < 12; j++) { float d = vals[j] - mean; s2 += d * d; }
        s2 = warp_sum(s2);
        float rstd = rsqrtf(s2 * (1.0f/CHN) + 1e-5f);

        size_t row = ((size_t)b * NTOK + tok) * CHN;
        #pragma unroll
        for (int j = 0; j < 12; j++) {
            int cidx = lane + 32*j;
            float v = vals[j];
            xt[row + cidx] = v;
            cur[row + cidx] = __float2half((v - mean) * rstd * g[cidx] + bt[cidx]);
        }
    }
}

// ---------------- token-major depthwise 3x3 + residual ----------------
__global__ void dwconv_tok(const float* __restrict__ t, const float* __restrict__ w,
                           const float* __restrict__ bias, float* __restrict__ y)
{
    __shared__ float sw[CHN*9];
    int b = blockIdx.y, h = blockIdx.x;
    int c = threadIdx.x;                 // 384 threads
    for (int i = c; i < CHN*9; i += CHN) sw[i] = w[i];
    __syncthreads();

    float wr[9];
    #pragma unroll
    for (int j = 0; j < 9; j++) wr[j] = sw[c*9 + j];
    float bb = bias[c];

    const float* tb = t + (size_t)b * NTOK * CHN;
    float* yb = y + (size_t)b * NTOK * CHN;

    for (int q = 0; q < WW; q++) {
        float acc = bb;
        float center = 0.f;
        #pragma unroll
        for (int dh = -1; dh <= 1; dh++) {
            int hh = h + dh;
            if ((unsigned)hh >= HH) continue;
            #pragma unroll
            for (int dw = -1; dw <= 1; dw++) {
                int ww2 = q + dw;
                if ((unsigned)ww2 >= WW) continue;
                float val = __ldg(tb + (size_t)(hh*WW + ww2) * CHN + c);
                acc += wr[(dh+1)*3 + (dw+1)] * val;
                if (dh == 0 && dw == 0) center = val;
            }
        }
        yb[(size_t)(h*WW + q) * CHN + c] = center + acc;
    }
}

// ---------------- layernorm (token-major in) -> fp16 ----------------
__global__ void layernorm_h(const float* __restrict__ in, const float* __restrict__ g,
                            const float* __restrict__ bt, __half* __restrict__ out)
{
    int row = blockIdx.x;
    int tid = threadIdx.x;          // 128
    int lane = tid & 31, wid = tid >> 5;
    const float* ip = in + (size_t)row * CHN;

    float v0 = ip[tid], v1 = ip[tid+128], v2 = ip[tid+256];
    __shared__ float sred[8];

    float s = warp_sum(v0 + v1 + v2);
    if (lane == 0) sred[wid] = s;
    __syncthreads();
    float mean = (sred[0]+sred[1]+sred[2]+sred[3]) * (1.0f/CHN);

    float d0 = v0-mean, d1 = v1-mean, d2 = v2-mean;
    float s2 = warp_sum(d0*d0 + d1*d1 + d2*d2);
    if (lane == 0) sred[4+wid] = s2;
    __syncthreads();
    float var = (sred[4]+sred[5]+sred[6]+sred[7]) * (1.0f/CHN);
    float rstd = rsqrtf(var + 1e-5f);

    __half* op = out + (size_t)row * CHN;
    op[tid]     = __float2half(d0*rstd*g[tid]     + bt[tid]);
    op[tid+128] = __float2half(d1*rstd*g[tid+128] + bt[tid+128]);
    op[tid+256] = __float2half(d2*rstd*g[tid+256] + bt[tid+256]);
}

// ---------------- channel attention: K^T V + fused softmax -> fp16 attn ----------------
__global__ void attn_kv_sm(const __half* __restrict__ qkv, __half* __restrict__ attn)
{
    int bh = blockIdx.x;
    int b = bh / HEADS, h = bh % HEADS;
    const __half* kb = qkv + (size_t)b * NTOK * (3*CHN) + CHN   + h*HDIM;
    const __half* vb = qkv + (size_t)b * NTOK * (3*CHN) + 2*CHN + h*HDIM;

    __shared__ float ks[32][33], vs[32][33];
    int e  = threadIdx.x & 31;
    int dg = threadIdx.x >> 5;
    float acc[4] = {0.f, 0.f, 0.f, 0.f};

    for (int n0 = 0; n0 < NTOK; n0 += 32) {
        #pragma unroll
        for (int r = 0; r < 4; r++) {
            int nl = (threadIdx.x >> 5) + r*8;
            int n = n0 + nl;
            ks[nl][e] = (n < NTOK) ? __half2float(kb[(size_t)n * (3*CHN) + e]) : 0.f;
            vs[nl][e] = (n < NTOK) ? __half2float(vb[(size_t)n * (3*CHN) + e]) : 0.f;
        }
        __syncthreads();
        #pragma unroll 8
        for (int nl = 0; nl < 32; nl++) {
            float vv = vs[nl][e];
            #pragma unroll
            for (int i = 0; i < 4; i++) acc[i] = fmaf(ks[nl][dg + 8*i], vv, acc[i]);
        }
        __syncthreads();
    }
    #pragma unroll
    for (int i = 0; i < 4; i++) {
        float v = acc[i] * SCALE_K;
        float mx = warp_max(v);
        float ex = expf(v - mx);
        float s = warp_sum(ex);
        int d = dg + 8*i;
        attn[(size_t)bh * (HDIM*HDIM) + d*HDIM + e] = __float2half(ex / s);
    }
}

// ---------------- tensor-core attention apply: ao = q @ attn^T ----------------
// Per block: (b,h), 64-token tile, 128 threads (4 warps, each one 16-row m-tile).
// A = q rows [m][e] fp16; B = attn rows [d][e] fp16 (pre-converted). smem 64B rows,
// swizzle c' = c ^ (r&3).  M=64, N=32, K=32 (2 k-steps).
__global__ void __launch_bounds__(128) attn_apply_mma(
    const __half* __restrict__ qkv, const __half* __restrict__ attn,
    __half* __restrict__ out)
{
    __shared__ __align__(128) __half qs[64*32];    // 4KB, swizzled
    __shared__ __align__(128) __half as[32*32];    // 2KB, swizzled
    uint32_t sq = smem_u32(qs);
    uint32_t sa = smem_u32(as);

    int bh = blockIdx.x;
    int b = bh / HEADS, h = bh % HEADS;
    int m0 = blockIdx.y * 64;
    int tid = threadIdx.x, lane = tid & 31, w = tid >> 5;

    // load q tile: 64 rows x 4 chunks (16B each); 256 chunks over 128 threads
    const __half* qb = qkv + (size_t)b * NTOK * (3*CHN) + h*HDIM;
    #pragma unroll
    for (int i = 0; i < 2; i++) {
        int id = tid + (i << 7);
        int r = id >> 2, c = id & 3;
        uint32_t d = sq + (r << 6) + ((c ^ (r & 3)) << 4);
        int m = m0 + r;
        uint4 v = make_uint4(0u, 0u, 0u, 0u);
        if (m < NTOK) v = *(const uint4*)(qb + (size_t)m * (3*CHN) + (c << 3));
        *(uint4*)((char*)qs + (d - sq)) = v;
    }
    // load attn 32x32 fp16: 32 rows x 4 chunks = 128 chunks, one per thread
    {
        int r = tid >> 2, c = tid & 3;
        const __half* ap = attn + (size_t)bh * (HDIM*HDIM) + r * HDIM + (c << 3);
        uint32_t d = sa + (r << 6) + ((c ^ (r & 3)) << 4);
        *(uint4*)((char*)as + (d - sa)) = *(const uint4*)ap;
    }
    __syncthreads();

    float acc[4][4];
    #pragma unroll
    for (int i = 0; i < 4; i++)
        #pragma unroll
        for (int q = 0; q < 4; q++) acc[i][q] = 0.f;

    #pragma unroll
    for (int ks = 0; ks < 2; ks++) {
        uint32_t a[4], bfr[4][2];
        {   // A frag: rows w*16 + (lane&15), chunk kc = 2ks + (lane>>4)
            uint32_t r = (w << 4) + (lane & 15);
            uint32_t kc = (ks << 1) + (lane >> 4);
            uint32_t addr = sq + (r << 6) + ((kc ^ (r & 3)) << 4);
            LDMX4(a[0], a[1], a[2], a[3], addr);
        }
        #pragma unroll
        for (int ntp = 0; ntp < 2; ntp++) {
            uint32_t j = lane >> 3;
            uint32_t nt = ntp * 2 + (j >> 1);
            uint32_t kc = (ks << 1) + (j & 1);
            uint32_t r = nt * 8 + (lane & 7);
            uint32_t addr = sa + (r << 6) + ((kc ^ (r & 3)) << 4);
            uint32_t q0, q1, q2, q3;
            LDMX4(q0, q1, q2, q3, addr);
            bfr[ntp*2][0] = q0;   bfr[ntp*2][1] = q1;
            bfr[ntp*2+1][0] = q2; bfr[ntp*2+1][1] = q3;
        }
        #pragma unroll
        for (int nt = 0; nt < 4; nt++)
            MMA16816(acc[nt], a, bfr[nt]);
    }

    // epilogue
    __half* ob = out + (size_t)b * NTOK * CHN + h*HDIM;
    int mrow = (w << 4) + (lane >> 2);
    int ncol = (lane & 3) * 2;
    #pragma unroll
    for (int nt = 0; nt < 4; nt++) {
        int n = nt * 8 + ncol;
        int m = m0 + mrow;
        if (m < NTOK) {
            __half2 p; p.x = __float2half(acc[nt][0]); p.y = __float2half(acc[nt][1]);
            *(__half2*)(ob + (size_t)m * CHN + n) = p;
        }
        if (m + 8 < NTOK) {
            __half2 p; p.x = __float2half(acc[nt][2]); p.y = __float2half(acc[nt][3]);
            *(__half2*)(ob + (size_t)(m+8) * CHN + n) = p;
        }
    }
}

// ---------------- host launcher ----------------
extern "C" void kernel_launch(void* const* d_in, const int* in_sizes, int n_in,
                              void* d_out, int out_size)
{
    const float* x      = (const float*)d_in[0];
    const float* cpe1_w = (const float*)d_in[1];
    const float* cpe1_b = (const float*)d_in[2];
    const float* n1_g   = (const float*)d_in[3];
    const float* n1_b   = (const float*)d_in[4];
    const float* qkv_w  = (const float*)d_in[5];
    const float* proj_w = (const float*)d_in[6];
    const float* proj_b = (const float*)d_in[7];
    const float* cpe2_w = (const float*)d_in[8];
    const float* cpe2_b = (const float*)d_in[9];
    const float* n2_g   = (const float*)d_in[10];
    const float* n2_b   = (const float*)d_in[11];
    const float* fc1_w  = (const float*)d_in[12];
    const float* fc1_b  = (const float*)d_in[13];
    const float* fc2_w  = (const float*)d_in[14];
    const float* fc2_b  = (const float*)d_in[15];
    float* out = (float*)d_out;

    float *p_nchwA, *p_xt, *p_x2, *p_x3;
    __half *p_attnH, *p_qkvH, *p_curH, *p_aoH, *p_hidH, *p_wqkvH, *p_wprojH, *p_wfc1H, *p_wfc2H;
    cudaGetSymbolAddress((void**)&p_nchwA,  g_nchwA);
    cudaGetSymbolAddress((void**)&p_xt,     g_xt);
    cudaGetSymbolAddress((void**)&p_x2,     g_x2);
    cudaGetSymbolAddress((void**)&p_x3,     g_x3);
    cudaGetSymbolAddress((void**)&p_attnH,  g_attnH);
    cudaGetSymbolAddress((void**)&p_qkvH,   g_qkvH);
    cudaGetSymbolAddress((void**)&p_curH,   g_curH);
    cudaGetSymbolAddress((void**)&p_aoH,    g_aoH);
    cudaGetSymbolAddress((void**)&p_hidH,   g_hidH);
    cudaGetSymbolAddress((void**)&p_wqkvH,  g_wqkvH);
    cudaGetSymbolAddress((void**)&p_wprojH, g_wprojH);
    cudaGetSymbolAddress((void**)&p_wfc1H,  g_wfc1H);
    cudaGetSymbolAddress((void**)&p_wfc2H,  g_wfc2H);

    cudaFuncSetAttribute(gemm_mma, cudaFuncAttributeMaxDynamicSharedMemorySize, GEMM_SMEM);
    cudaFuncSetAttribute(trans_ln, cudaFuncAttributeMaxDynamicSharedMemorySize, TLN_SMEM);

    // weight converts (single launch)
    weight_conv_all<<<dim3((HIDDEN*CHN + 255)/256, 4), 256>>>(
        qkv_w, p_wqkvH, proj_w, p_wprojH, fc1_w, p_wfc1H, fc2_w, p_wfc2H);

    // 1) x = x + dwconv1(x)            (NCHW)
    dwconv_res<<<BATCH*CHN, 256>>>(x, cpe1_w, cpe1_b, p_nchwA);
    // 2) fused transpose + LN1: xt (fp32 token-major) + curH (fp16)
    trans_ln<<<dim3(25, BATCH), 256, TLN_SMEM>>>(p_nchwA, n1_g, n1_b, p_xt, p_curH);
    // 3) qkvH = cur @ qkv_w^T          (fp16 out)
    gemm_mma<<<dim3((3*CHN)/128, MROWS/128), 256, GEMM_SMEM>>>(
        p_curH, p_wqkvH, nullptr, nullptr, nullptr, p_qkvH, 3*CHN, CHN, 2);
    // 4) channel attention: K^T V + softmax fused (fp16 attn), tensor-core apply
    attn_kv_sm<<<BATCH*HEADS, 256>>>(p_qkvH, p_attnH);
    attn_apply_mma<<<dim3(BATCH*HEADS, 13), 128>>>(p_qkvH, p_attnH, p_aoH);
    // 5) x2 = xt + ao @ proj_w^T + proj_b
    gemm_mma<<<dim3(CHN/128, MROWS/128), 256, GEMM_SMEM>>>(
        p_aoH, p_wprojH, proj_b, p_xt, p_x2, nullptr, CHN, CHN, 0);
    // 6) x3 = x2 + dwconv2(x2)          (token-major)
    dwconv_tok<<<dim3(HH, BATCH), CHN>>>(p_x2, cpe2_w, cpe2_b, p_x3);
    // 7) curH = fp16(LN2(x3))
    layernorm_h<<<MROWS, 128>>>(p_x3, n2_g, n2_b, p_curH);
    // 8) hidH = fp16(gelu(cur @ fc1^T + b1))
    gemm_mma<<<dim3(HIDDEN/128, MROWS/128), 256, GEMM_SMEM>>>(
        p_curH, p_wfc1H, fc1_b, nullptr, nullptr, p_hidH, HIDDEN, CHN, 1);
    // 9) out(NCHW) = transpose(x3 + hid @ fc2^T + b2)   -- fused epilogue
    gemm_mma<<<dim3(CHN/128, MROWS/128), 256, GEMM_SMEM>>>(
        p_hidH, p_wfc2H, fc2_b, p_x3, out, nullptr, CHN, HIDDEN, 3);
}